// round 17
// baseline (speedup 1.0000x reference)
#include <cuda_runtime.h>

namespace {

constexpr int BATCH = 16;
constexpr int DIM   = 48;
constexpr int HID   = 16;
constexpr int CC    = 8;
constexpr int Hh    = 256;
constexpr int Ww    = 256;
constexpr int HW    = Hh * Ww;
constexpr float LN_EPS = 1e-5f;
constexpr int THREADS = 256;
constexpr int TPB1   = 256;   // tokens per block in k_front (2 tokens per thread, 2 thr-roles)
constexpr int XSTRIDE = 52;   // padded token stride in smem floats

// intermediate, token-interleaved: g_mid[token][16]; ch 0..7 = x1, 8..15 = LN(x2)
__device__ float g_mid[(size_t)BATCH * HW * HID];

__device__ __forceinline__ float tanh_fast(float x) {
    float y;
    asm("tanh.approx.f32 %0, %1;" : "=f"(y) : "f"(x));
    return y;
}

// tanh-form GELU
__device__ __forceinline__ float gelu_f(float v) {
    const float t = v * v;
    const float inner = fmaf(0.044715f * t, v, v);
    const float h = tanh_fast(0.79788456080286536f * inner);
    const float hv = 0.5f * v;
    return fmaf(hv, h, hv);
}

// ---- packed f32x2 helpers ----
__device__ __forceinline__ unsigned long long pk2(float lo, float hi) {
    unsigned long long r;
    asm("mov.b64 %0, {%1, %2};" : "=l"(r) : "f"(lo), "f"(hi));
    return r;
}
__device__ __forceinline__ void upk2(unsigned long long v, float& lo, float& hi) {
    asm("mov.b64 {%0, %1}, %2;" : "=f"(lo), "=f"(hi) : "l"(v));
}
__device__ __forceinline__ void ffma2(unsigned long long& d,
                                      unsigned long long a, unsigned long long b) {
    asm("fma.rn.f32x2 %0, %1, %2, %3;" : "=l"(d) : "l"(a), "l"(b), "l"(d));
}
__device__ __forceinline__ unsigned long long mul2(unsigned long long a, unsigned long long b) {
    unsigned long long r;
    asm("mul.rn.f32x2 %0, %1, %2;" : "=l"(r) : "l"(a), "l"(b));
    return r;
}

// ---------------- Kernel 1: token GEMM 48->16, 2 tokens/thread (R15 proven) ----------------
__global__ __launch_bounds__(THREADS, 3)
void k_front(const float* __restrict__ x,
             const float* __restrict__ gW1, const float* __restrict__ gb1,
             const float* __restrict__ ggamma, const float* __restrict__ gbeta)
{
    __shared__ __align__(16) float sW1[DIM * HID];
    __shared__ float sb1[HID];
    __shared__ float sG[CC], sBt[CC];
    extern __shared__ __align__(16) float sX[];      // 256 tokens * 52 floats

    const int tid = threadIdx.x;
    for (int i = tid; i < DIM * HID; i += THREADS) sW1[i] = gW1[i];
    if (tid < HID) sb1[tid] = gb1[tid];
    if (tid < CC)  { sG[tid] = ggamma[tid]; sBt[tid] = gbeta[tid]; }

    const float4* xg4 = (const float4*)x;
    const size_t base4 = (size_t)blockIdx.x * TPB1 * (DIM / 4);
    #pragma unroll
    for (int i = tid; i < TPB1 * (DIM / 4); i += THREADS) {
        const int tok = i / (DIM / 4);
        const int e4  = i - tok * (DIM / 4);
        *(float4*)(sX + tok * XSTRIDE + e4 * 4) = xg4[base4 + i];
    }
    __syncthreads();

    const int role = tid >> 7;
    const int lt   = tid & 127;
    const int jbase = role * CC;
    const float4* xpA = (const float4*)(sX + lt * XSTRIDE);
    const float4* xpB = (const float4*)(sX + (lt + 128) * XSTRIDE);

    unsigned long long ypA[4], ypB[4];
    ypA[0] = pk2(sb1[jbase + 0], sb1[jbase + 1]);
    ypA[1] = pk2(sb1[jbase + 2], sb1[jbase + 3]);
    ypA[2] = pk2(sb1[jbase + 4], sb1[jbase + 5]);
    ypA[3] = pk2(sb1[jbase + 6], sb1[jbase + 7]);
    ypB[0] = ypA[0]; ypB[1] = ypA[1]; ypB[2] = ypA[2]; ypB[3] = ypA[3];

    #pragma unroll 1
    for (int ch = 0; ch < 6; ++ch) {
        const float4 a0 = xpA[ch * 2 + 0], a1 = xpA[ch * 2 + 1];
        const float4 b0 = xpB[ch * 2 + 0], b1 = xpB[ch * 2 + 1];
        const float xsA[8] = {a0.x, a0.y, a0.z, a0.w, a1.x, a1.y, a1.z, a1.w};
        const float xsB[8] = {b0.x, b0.y, b0.z, b0.w, b1.x, b1.y, b1.z, b1.w};
        #pragma unroll
        for (int k = 0; k < 8; ++k) {
            const int d = ch * 8 + k;
            const ulonglong2* wp = (const ulonglong2*)(sW1 + d * HID + jbase);
            const ulonglong2 wA = wp[0], wB = wp[1];
            const unsigned long long xa = pk2(xsA[k], xsA[k]);
            const unsigned long long xb = pk2(xsB[k], xsB[k]);
            ffma2(ypA[0], xa, wA.x);
            ffma2(ypB[0], xb, wA.x);
            ffma2(ypA[1], xa, wA.y);
            ffma2(ypB[1], xb, wA.y);
            ffma2(ypA[2], xa, wB.x);
            ffma2(ypB[2], xb, wB.x);
            ffma2(ypA[3], xa, wB.y);
            ffma2(ypB[3], xb, wB.y);
        }
    }

    const int t0 = blockIdx.x * TPB1 + lt;

    #pragma unroll
    for (int half = 0; half < 2; ++half) {
        float y[CC];
        unsigned long long* yp = half ? ypB : ypA;
        upk2(yp[0], y[0], y[1]);
        upk2(yp[1], y[2], y[3]);
        upk2(yp[2], y[4], y[5]);
        upk2(yp[3], y[6], y[7]);

        #pragma unroll
        for (int j = 0; j < CC; ++j) y[j] = gelu_f(gelu_f(y[j]));

        const int t = t0 + half * 128;
        float* mb = g_mid + (size_t)t * HID + role * CC;

        if (role == 0) {
            *(float4*)(mb + 0) = make_float4(y[0], y[1], y[2], y[3]);
            *(float4*)(mb + 4) = make_float4(y[4], y[5], y[6], y[7]);
        } else {
            float m = 0.0f;
            #pragma unroll
            for (int c = 0; c < CC; ++c) m += y[c];
            m *= 0.125f;
            float var = 0.0f;
            #pragma unroll
            for (int c = 0; c < CC; ++c) { const float dd = y[c] - m; var = fmaf(dd, dd, var); }
            const float inv = rsqrtf(var * 0.125f + LN_EPS);
            float n[CC];
            #pragma unroll
            for (int c = 0; c < CC; ++c) n[c] = (y[c] - m) * inv * sG[c] + sBt[c];
            *(float4*)(mb + 0) = make_float4(n[0], n[1], n[2], n[3]);
            *(float4*)(mb + 4) = make_float4(n[4], n[5], n[6], n[7]);
        }
    }
}

// ---------------- Kernel 2: dw3x3 + pw1x1 + gate + GEMM 8->48, 2 px/thread ----------------
constexpr int TH2 = 8;
constexpr int TW2 = 64;
constexpr int PH2 = TH2 + 2;   // 10
constexpr int PW2 = TW2 + 2;   // 66
constexpr int NT2 = PH2 * PW2; // 660

__global__ __launch_bounds__(THREADS, 4)
void k_back(const float* __restrict__ gdww, const float* __restrict__ gdwb,
            const float* __restrict__ gpww, const float* __restrict__ gpwb,
            const float* __restrict__ gW2, const float* __restrict__ gb2,
            float* __restrict__ out)
{
    __shared__ __align__(16) float sTile[CC][NT2];   // planar, stride-2 taps (2-way max)
    __shared__ __align__(16) float sW2d[CC * DIM * 2];  // dup pairs [c][d][2]
    __shared__ __align__(16) float sb2d[DIM * 2];       // dup bias
    __shared__ __align__(16) float sPwd[CC * CC * 2];   // dup pw [c][cin][2]
    __shared__ float sPwb[CC];
    __shared__ __align__(16) float sDw[CC * 12];        // padded dw rows
    __shared__ float sDwb[CC];

    const int tid = threadIdx.x;
    for (int i = tid; i < CC * DIM * 2; i += THREADS) {     // 768
        const int c = i / (DIM * 2), rem = i - c * (DIM * 2);
        sW2d[i] = gW2[c * DIM + rem / 2];
    }
    if (tid < DIM * 2)  sb2d[tid] = gb2[tid / 2];
    if (tid < CC * CC * 2) {
        const int c = tid / (CC * 2), rem = tid - c * (CC * 2);
        sPwd[tid] = gpww[c * CC + rem / 2];
    }
    if (tid < CC * 12) {
        const int c = tid / 12, tap = tid - c * 12;
        sDw[tid] = (tap < 9) ? gdww[c * 9 + tap] : 0.0f;
    }
    if (tid < CC) { sPwb[tid] = gpwb[tid]; sDwb[tid] = gdwb[tid]; }

    const int b  = blockIdx.z;
    const int h0 = blockIdx.y * TH2;
    const int w0 = blockIdx.x * TW2;

    // halo'd tile fill (2 LDG.128 per pixel, planar scatter)
    #pragma unroll 1
    for (int p = tid; p < NT2; p += THREADS) {
        const int py = p / PW2;
        const int px = p - py * PW2;
        const int gh = h0 + py - 1;
        const int gw = w0 + px - 1;
        float4 a = make_float4(0.f, 0.f, 0.f, 0.f);
        float4 bq = a;
        if ((unsigned)gh < (unsigned)Hh && (unsigned)gw < (unsigned)Ww) {
            const float* mp = g_mid + (size_t)(b * HW + gh * Ww + gw) * HID + CC;
            a  = *(const float4*)(mp + 0);
            bq = *(const float4*)(mp + 4);
        }
        sTile[0][p] = a.x;  sTile[1][p] = a.y;  sTile[2][p] = a.z;  sTile[3][p] = a.w;
        sTile[4][p] = bq.x; sTile[5][p] = bq.y; sTile[6][p] = bq.z; sTile[7][p] = bq.w;
    }
    __syncthreads();

    const int ty  = tid >> 5;          // 0..7
    const int txp = tid & 31;          // pixel pair index
    const int col0 = txp * 2;          // padded window start (even -> float2 aligned)
    const int pix0 = (h0 + ty) * Ww + (w0 + txp * 2);

    // ---- dw 3x3 for both pixels; capture centers for pw ----
    unsigned long long acc2[CC], ncen2[CC];
    #pragma unroll
    for (int c = 0; c < CC; ++c) {
        const float* tp = sTile[c] + ty * PW2 + col0;
        const float2 a0 = *(const float2*)(tp);
        const float2 b0 = *(const float2*)(tp + 2);
        const float2 a1 = *(const float2*)(tp + PW2);
        const float2 b1 = *(const float2*)(tp + PW2 + 2);
        const float2 a2 = *(const float2*)(tp + 2 * PW2);
        const float2 b2v = *(const float2*)(tp + 2 * PW2 + 2);
        const float4 ka = *(const float4*)(sDw + c * 12 + 0);
        const float4 kb = *(const float4*)(sDw + c * 12 + 4);
        const float  k8 = sDw[c * 12 + 8];
        float p0 = sDwb[c], p1 = p0;
        p0 = fmaf(a0.x, ka.x, p0);  p1 = fmaf(a0.y, ka.x, p1);
        p0 = fmaf(a0.y, ka.y, p0);  p1 = fmaf(b0.x, ka.y, p1);
        p0 = fmaf(b0.x, ka.z, p0);  p1 = fmaf(b0.y, ka.z, p1);
        p0 = fmaf(a1.x, ka.w, p0);  p1 = fmaf(a1.y, ka.w, p1);
        p0 = fmaf(a1.y, kb.x, p0);  p1 = fmaf(b1.x, kb.x, p1);
        p0 = fmaf(b1.x, kb.y, p0);  p1 = fmaf(b1.y, kb.y, p1);
        p0 = fmaf(a2.x, kb.z, p0);  p1 = fmaf(a2.y, kb.z, p1);
        p0 = fmaf(a2.y, kb.w, p0);  p1 = fmaf(b2v.x, kb.w, p1);
        p0 = fmaf(b2v.x, k8, p0);   p1 = fmaf(b2v.y, k8, p1);
        acc2[c] = pk2(p0, p1);
        ncen2[c] = pk2(a1.y, b1.x);   // centers of the two pixels
    }

    // ---- x1 gate halves for both pixels ----
    const float4* xq0 = (const float4*)(g_mid + (size_t)(b * HW + pix0) * HID);
    const float4 q0a = __ldg(xq0 + 0), q0b = __ldg(xq0 + 1);
    const float4* xq1 = (const float4*)(g_mid + (size_t)(b * HW + pix0 + 1) * HID);
    const float4 q1a = __ldg(xq1 + 0), q1b = __ldg(xq1 + 1);
    unsigned long long x1_2[CC];
    x1_2[0] = pk2(q0a.x, q1a.x); x1_2[1] = pk2(q0a.y, q1a.y);
    x1_2[2] = pk2(q0a.z, q1a.z); x1_2[3] = pk2(q0a.w, q1a.w);
    x1_2[4] = pk2(q0b.x, q1b.x); x1_2[5] = pk2(q0b.y, q1b.y);
    x1_2[6] = pk2(q0b.z, q1b.z); x1_2[7] = pk2(q0b.w, q1b.w);

    // ---- pw 1x1 packed over pixel pair (dup weights, no packs) + gate ----
    #pragma unroll
    for (int c = 0; c < CC; ++c) {
        unsigned long long chv = pk2(sPwb[c], sPwb[c]);
        const ulonglong2* pw = (const ulonglong2*)(sPwd + c * (CC * 2));
        const ulonglong2 wA = pw[0], wB = pw[1], wC = pw[2], wD = pw[3];
        ffma2(chv, ncen2[0], wA.x);
        ffma2(chv, ncen2[1], wA.y);
        ffma2(chv, ncen2[2], wB.x);
        ffma2(chv, ncen2[3], wB.y);
        ffma2(chv, ncen2[4], wC.x);
        ffma2(chv, ncen2[5], wC.y);
        ffma2(chv, ncen2[6], wD.x);
        ffma2(chv, ncen2[7], wD.y);
        acc2[c] = mul2(mul2(x1_2[c], acc2[c]), chv);   // now g2[c]
    }

    // ---- GEMM 8->48 packed over pixel pair; STG.64 stores ----
    float* op = out + (size_t)b * DIM * HW + pix0;
    #pragma unroll
    for (int dp = 0; dp < DIM / 2; ++dp) {
        const ulonglong2 bb = *(const ulonglong2*)(sb2d + dp * 4);
        unsigned long long a0 = bb.x, a1 = bb.y;
        #pragma unroll
        for (int c = 0; c < CC; ++c) {
            const ulonglong2 ww = *(const ulonglong2*)(sW2d + c * (DIM * 2) + dp * 4);
            ffma2(a0, acc2[c], ww.x);
            ffma2(a1, acc2[c], ww.y);
        }
        *(unsigned long long*)(op + (size_t)(dp * 2 + 0) * HW) = a0;
        *(unsigned long long*)(op + (size_t)(dp * 2 + 1) * HW) = a1;
    }
}

} // namespace

extern "C" void kernel_launch(void* const* d_in, const int* in_sizes, int n_in,
                              void* d_out, int out_size) {
    const float* x     = (const float*)d_in[0];
    const float* W1    = (const float*)d_in[1];
    const float* b1    = (const float*)d_in[2];
    const float* gamma = (const float*)d_in[3];
    const float* beta  = (const float*)d_in[4];
    const float* dw_w  = (const float*)d_in[5];
    const float* dw_b  = (const float*)d_in[6];
    const float* pw_w  = (const float*)d_in[7];
    const float* pw_b  = (const float*)d_in[8];
    const float* W2    = (const float*)d_in[9];
    const float* b2    = (const float*)d_in[10];
    float* out = (float*)d_out;

    const int dyn1 = TPB1 * XSTRIDE * (int)sizeof(float);   // 53248 B
    cudaFuncSetAttribute(k_front, cudaFuncAttributeMaxDynamicSharedMemorySize, dyn1);

    k_front<<<BATCH * HW / TPB1, THREADS, dyn1>>>(x, W1, b1, gamma, beta);

    dim3 grid2(Ww / TW2, Hh / TH2, BATCH);
    k_back<<<grid2, THREADS>>>(dw_w, dw_b, pw_w, pw_b, W2, b2, out);
}